// round 16
// baseline (speedup 1.0000x reference)
#include <cuda_runtime.h>
#include <math.h>

#define BATCH      262144
#define N_LEAVES   64
#define N_INTERNAL 63

#define CHILD_EPS  2.2204460492503131e-16
#define BYPASS_TH  0.9999999999999998   /* 1 - DBL_EPSILON */
#define CLAMP_V    1e300
#define PI_F       3.14159265358979f
#define LN2_F      0.69314718056f

// Folded parameters (built by prep kernel).
static __device__ double g_g  [N_INTERNAL * 8];  // folded gates (double, for fold step)
static __device__ float4 g_gf4[126];             // per side: (p0,p1,p2,p3) as float
static __device__ float4 g_r0f[N_LEAVES];        // round-0 folded coeffs per leaf

// 2/pi fraction bits (fdlibm two_over_pi), prepended zero word.
static __device__ const unsigned long long PH_TAB[21] = {
    0x0000000000000000ULL,
    0xA2F9836E4E441529ULL, 0xFC2757D1F534DDC0ULL, 0xDB6295993C439041ULL,
    0xFE5163ABDEBBC561ULL, 0xB7246E3A424DD2E0ULL, 0x06492EEA09D1921CULL,
    0xFE1DEB1CB129A73EULL, 0xE88235F52EBB4484ULL, 0xE99C7026B45F7E41ULL,
    0x3991D639835339F4ULL, 0x9C845F8BBDF9283BULL, 0x1FF897FFDE05980FULL,
    0xEF2F118B5A0A6D1FULL, 0x6D367ECF27CB09B7ULL, 0x4F463F669E5FEA2DULL,
    0x7527BAC7EBE5F17BULL, 0x3D0739F78A5292EAULL, 0x6BFB5FB11F8D5D08ULL,
    0x56033046FC7B6BABULL, 0xF0CFBC209AF4361DULL
};

// NaN unreachable post-round-0 -> pure min/max clamp matches nan_to_num+clip.
__device__ __forceinline__ double clampd(double v) {
    return fmin(fmax(v, -CLAMP_V), CLAMP_V);
}

// 2^k as double via high-word construct (single 32-bit shift).
__device__ __forceinline__ double pow2k(int kbiased) {
    return __hiloint2double(kbiased << 20, 0);
}

// Branchy sincos (float outputs): Cody-Waite (<1e6, single-DFMA) or 128-bit PH.
__device__ __forceinline__ void fast_sincos(const unsigned long long* __restrict__ ph,
                                            double a, float& sf, float& cf) {
    double aa = fabs(a);
    if (aa < 1.0e6) {
        double kd = rint(a * 0.15915494309189535);
        // kd <= 1.6e5; dropping the lo-term costs <= 4e-11 rad, << 1e-6 budget.
        double r  = fma(-kd, 6.283185307179586, a);
        __sincosf((float)r, &sf, &cf);
    } else {
        int hi = __double2hiint(aa);
        int E  = hi >> 20;                                  // biased exp (aa>0)
        unsigned long long ix = (__double_as_longlong(aa) & 0xFFFFFFFFFFFFFULL) | (1ULL << 52);
        int q = E - 1013;
        int i = q >> 6, sh = q & 63;
        unsigned long long p0 = ph[i], p1 = ph[i+1], p2 = ph[i+2];
        unsigned long long w0 = (p0 << sh) | ((p1 >> 1) >> (63 - sh));
        unsigned long long w1 = (p1 << sh) | ((p2 >> 1) >> (63 - sh));
        unsigned long long fhi = ix * w0 + __umul64hi(ix, w1);
        double fr  = (double)(long long)fhi * 5.421010862427522e-20;   // [-0.5,0.5)
        double ang = fr * 6.283185307179586;
        __sincosf((float)ang, &sf, &cf);
        sf = (a < 0.0) ? -sf : sf;
    }
}

// ---------------------------------------------------------------------------
// Prep: dtype detect, softmaxes, bypass-fold gates, fold leaves into round-0.
// ---------------------------------------------------------------------------
__global__ void prep_kernel(const void* __restrict__ leafv,
                            const void* __restrict__ gatev,
                            float* __restrict__ out,
                            int tail_mode, long long tail_off) {
    __shared__ int    s_is_f32;
    __shared__ double s_w[N_LEAVES * 3];
    int t = threadIdx.x;

    if (t == 0) {
        const float* lf = (const float*)leafv;
        int cnt = 0;
        for (int i = 0; i < 64; ++i) {
            float v = fabsf(lf[i]);
            if (isfinite(v) && v > 1e-4f && v < 100.0f) ++cnt;
        }
        s_is_f32 = (cnt >= 52) ? 1 : 0;
    }
    __syncthreads();
    const int f32w = s_is_f32;
    const float*  lf = (const float*) leafv;
    const double* ld = (const double*)leafv;
    const float*  gf = (const float*) gatev;
    const double* gd = (const double*)gatev;

    if (t < N_LEAVES) {
        double a = f32w ? (double)lf[3*t]   : ld[3*t];
        double b = f32w ? (double)lf[3*t+1] : ld[3*t+1];
        double c = f32w ? (double)lf[3*t+2] : ld[3*t+2];
        double m = fmax(a, fmax(b, c));
        double ea = exp(a - m), eb = exp(b - m), ec = exp(c - m);
        double inv = 1.0 / (ea + eb + ec);
        double w[3] = {ea*inv, eb*inv, ec*inv};
        for (int j = 0; j < 3; ++j) {
            s_w[3*t+j] = w[j];
            if (tail_mode == 1) out[tail_off + 3*t + j] = (float)w[j];
        }
    } else if (t < N_LEAVES + 2*N_INTERNAL) {
        int g = t - N_LEAVES;                      // 0..125
        double v0 = f32w ? (double)gf[4*g]   : gd[4*g];
        double v1 = f32w ? (double)gf[4*g+1] : gd[4*g+1];
        double v2 = f32w ? (double)gf[4*g+2] : gd[4*g+2];
        double v3 = f32w ? (double)gf[4*g+3] : gd[4*g+3];
        double m = fmax(fmax(v0, v1), fmax(v2, v3));
        double e0 = exp(v0-m), e1 = exp(v1-m), e2 = exp(v2-m), e3 = exp(v3-m);
        double inv = 1.0 / (e0 + e1 + e2 + e3);
        double p0 = e0*inv, p1 = e1*inv, p2 = e2*inv, p3 = e3*inv;
        if (tail_mode == 1) {
            out[tail_off + 3*N_LEAVES + 4*g]   = (float)p0;
            out[tail_off + 3*N_LEAVES + 4*g+1] = (float)p1;
            out[tail_off + 3*N_LEAVES + 4*g+2] = (float)p2;
            out[tail_off + 3*N_LEAVES + 4*g+3] = (float)p3;
        }
        if (p0 > BYPASS_TH) { p0 = 1.0; p1 = 0.0; p2 = 0.0; p3 = 0.0; }
        if (p1 > BYPASS_TH) { p0 = 0.0; p1 = 1.0; p2 = 0.0; p3 = 0.0; }
        if (p2 > BYPASS_TH) { p0 = 0.0; p1 = 0.0; p2 = 1.0; p3 = 0.0; }
        if (!(p3 > CHILD_EPS)) p3 = 0.0;
        g_g[4*g]   = p0; g_g[4*g+1] = p1; g_g[4*g+2] = p2; g_g[4*g+3] = p3;
        g_gf4[g]   = make_float4((float)p0, (float)p1, (float)p2, (float)p3);
    }
    __syncthreads();

    if (t < N_LEAVES) {
        const double* gp = &g_g[(t >> 1) * 8 + (t & 1) * 4];
        double c0 = gp[0] + gp[3] * s_w[3*t];
        double c1 = gp[1] + gp[3] * s_w[3*t+1];
        double c2 = gp[2] + gp[3] * s_w[3*t+2];
        g_r0f[t] = make_float4((float)c0, (float)c1, (float)c2, 0.0f);
    }
}

// ---------------------------------------------------------------------------
// Round-1 node: children fp32 (|re| <= ~2e11, im in {0,-pi}).
// ---------------------------------------------------------------------------
__device__ __forceinline__ void eval_node_r1(const float4* __restrict__ sf4,
                                             int node,
                                             float clrf, float clif,
                                             float crrf, float crif,
                                             float x0f, float x1f,
                                             double& olr, double& oli) {
    float4 L = sf4[2*node], R = sf4[2*node+1];
    float basel = fmaf(L.y, x0f, fmaf(L.z, x1f, L.x));
    float baser = fmaf(R.y, x0f, fmaf(R.z, x1f, R.x));
    float alr = fmaf(L.w, clrf, basel);
    float ali = L.w * clif;                         // |ali| <= pi
    float brr = fmaf(R.w, crrf, baser);
    float bri = R.w * crif;
    float ac  = fminf(fmaxf(alr, -708.0f), 709.7f);
    float kdf = rintf(ac * 1.44269504f);
    float rf  = fmaf(-kdf, 0.693115234375f, ac);
    rf        = fmaf(-kdf, 3.1946183e-5f, rf);
    float ef2 = exp2f(fmaf(rf, 1.44269504f, 1.0f));   // 2*e^rf
    double sden = pow2k((int)kdf + 1022);
    float sf, cf;
    __sincosf(ali, &sf, &cf);
    float m2  = fmaxf(fmaf(brr, brr, bri * bri), 1.2e-38f);
    float grf = 0.5f * __log2f(m2) * LN2_F;
    float gif = atan2f(bri, brr);
    olr = clampd(fma((double)(ef2 * cf), sden, -(double)grf));
    oli = clampd(fma((double)(ef2 * sf), sden, -(double)gif));
}

// ---------------------------------------------------------------------------
// Full-range node (rounds 2-5): fp32-steered exp reduction (kd from fp32
// image, remainder from double alr, single DFMA), fp32 clog epilogue.
// ---------------------------------------------------------------------------
__device__ __forceinline__ void eval_node_full(const float4* __restrict__ sf4,
                                               int node,
                                               const unsigned long long* __restrict__ ph,
                                               double clr, double cli,
                                               double crr, double cri,
                                               float x0f, float x1f,
                                               double& olr, double& oli) {
    float4 L = sf4[2*node], R = sf4[2*node+1];
    double p3l = (double)L.w, p3r = (double)R.w;
    float basel = fmaf(L.y, x0f, fmaf(L.z, x1f, L.x));
    float baser = fmaf(R.y, x0f, fmaf(R.z, x1f, R.x));
    double alr = fma(p3l, clr, (double)basel);
    double ali = p3l * cli;
    double brr = fma(p3r, crr, (double)baser);
    double bri = p3r * cri;
    // exp(alr): kd from fp32 image (may differ by +-1; r from DOUBLE alr so
    // only |r| grows to <=1.05 -- exp2f still accurate). Saturation: alr>709.7
    // -> kd=1024 but r huge -> exp2f(+big)=inf -> clamp; alr<-708 -> 0.
    float acf = fminf(fmaxf((float)alr, -708.0f), 709.7f);
    float kdf = rintf(acf * 1.44269504f);
    double r  = fma(-(double)kdf, 0.6931471805599453, alr);
    r = fmin(fmax(r, -90.0), 90.0);     // bound for saturated alr (exp2f arg)
    float ef2 = exp2f(fmaf((float)r, 1.44269504f, 1.0f));   // 2*e^r
    double sden = pow2k((int)kdf + 1022);
    float sf, cf;
    fast_sincos(ph, ali, sf, cf);
    // clog with 2^k scaling; exponents via high words only.
    int ex = (__double2hiint(brr) >> 20) & 0x7ff;
    int ey = (__double2hiint(bri) >> 20) & 0x7ff;
    int em = ex > ey ? ex : ey;
    double sc = pow2k(2045 - em);                           // 2^(1022-em)
    float xsf = (float)(brr * sc), ysf = (float)(bri * sc);
    float m2  = fmaxf(fmaf(xsf, xsf, ysf * ysf), 1.2e-38f);
    float grf = fmaf(0.5f, __log2f(m2), (float)(em - 1022)) * LN2_F;
    float gif = atan2f(ysf, xsf);
    olr = clampd(fma((double)(ef2 * cf), sden, -(double)grf));
    oli = clampd(fma((double)(ef2 * sf), sden, -(double)gif));
}

// ---------------------------------------------------------------------------
// Main kernel: 2 lanes per element; lane-local through round 4, one shfl.
// ---------------------------------------------------------------------------
__global__ __launch_bounds__(128)
void tree_kernel(const float* __restrict__ x, float* __restrict__ out,
                 int interleaved) {
    __shared__ float4 sr0[N_LEAVES];
    __shared__ float4 sf4[126];
    __shared__ unsigned long long sph[21];
    int tid = threadIdx.x;
    for (int i = tid; i < N_LEAVES; i += 128) sr0[i] = g_r0f[i];
    for (int i = tid; i < 126; i += 128)      sf4[i] = g_gf4[i];
    if (tid < 21) sph[tid] = PH_TAB[tid];
    __syncthreads();

    int g    = blockIdx.x * 128 + tid;
    int e    = g >> 1;
    int lane = g & 1;

    float x0f = x[2*e];
    float x1f = x[2*e+1];

    // Round 0: 16 real pairs for this lane, fully fp32.
    float lrf[16], lif[16];
#pragma unroll
    for (int k = 0; k < 16; ++k) {
        int gk = 16*lane + k;
        float4 L = sr0[2*gk], R = sr0[2*gk+1];
        float bl = fmaf(L.y, x0f, fmaf(L.z, x1f, L.x));
        float br = fmaf(R.y, x0f, fmaf(R.z, x1f, R.x));
        float er = __expf(bl);
        float gr = __log2f(fmaxf(fabsf(br), 1e-30f)) * LN2_F;
        lrf[k] = er - gr;
        lif[k] = signbit(br) ? -PI_F : 0.0f;
    }

    // Round 1: 8 fp32 front-end nodes; outputs become double.
    double lr[8], li[8];
#pragma unroll
    for (int j = 0; j < 8; ++j)
        eval_node_r1(sf4, 32 + 8*lane + j,
                     lrf[2*j], lif[2*j], lrf[2*j+1], lif[2*j+1],
                     x0f, x1f, lr[j], li[j]);

    // Round 2: 4 nodes.
#pragma unroll
    for (int j = 0; j < 4; ++j)
        eval_node_full(sf4, 48 + 4*lane + j, sph,
                       lr[2*j], li[2*j], lr[2*j+1], li[2*j+1],
                       x0f, x1f, lr[j], li[j]);

    // Round 3: 2 nodes.
#pragma unroll
    for (int j = 0; j < 2; ++j)
        eval_node_full(sf4, 56 + 2*lane + j, sph,
                       lr[2*j], li[2*j], lr[2*j+1], li[2*j+1],
                       x0f, x1f, lr[j], li[j]);

    // Round 4: 1 node, still lane-local.
    eval_node_full(sf4, 60 + lane, sph,
                   lr[0], li[0], lr[1], li[1], x0f, x1f, lr[0], li[0]);

    // Round 5: node 62; right child comes from lane 1 via shfl.
    {
        double pr = __shfl_xor_sync(0xffffffffu, lr[0], 1);
        double pi = __shfl_xor_sync(0xffffffffu, li[0], 1);
        eval_node_full(sf4, 62, sph,
                       lr[0], li[0], pr, pi, x0f, x1f, lr[0], li[0]);
    }

    if (lane == 0) {
        if (interleaved) {
            out[2*e]   = (float)lr[0];
            out[2*e+1] = (float)li[0];
        } else {
            out[e] = (float)lr[0];
        }
    }
}

// ---------------------------------------------------------------------------
extern "C" void kernel_launch(void* const* d_in, const int* in_sizes, int n_in,
                              void* d_out, int out_size) {
    const float* x    = nullptr;
    const void*  leaf = nullptr;
    const void*  gate = nullptr;
    for (int i = 0; i < n_in; ++i) {
        if      (in_sizes[i] == 2 * BATCH)      x    = (const float*)d_in[i];
        else if (in_sizes[i] == 3 * N_LEAVES)   leaf = d_in[i];
        else if (in_sizes[i] == 8 * N_INTERNAL) gate = d_in[i];
    }
    if (!x || !leaf || !gate) return;

    float* out = (float*)d_out;

    const int NPROB = 3*N_LEAVES + 8*N_INTERNAL;  // 696
    int interleaved, tail_mode = 0;
    long long tail_off = 0;

    if (out_size >= 2*BATCH + NPROB) {
        interleaved = 1; tail_mode = 1; tail_off = 2*BATCH;
    } else if (out_size >= 2*BATCH) {
        interleaved = 1;
    } else if (out_size >= BATCH + NPROB) {
        interleaved = 0; tail_mode = 1; tail_off = BATCH;
    } else {
        interleaved = 0;
    }

    prep_kernel<<<1, 192>>>(leaf, gate, out, tail_mode, tail_off);
    tree_kernel<<<(BATCH*2)/128, 128>>>(x, out, interleaved);
}

// round 17
// speedup vs baseline: 1.4012x; 1.4012x over previous
#include <cuda_runtime.h>
#include <math.h>

#define BATCH      262144
#define N_LEAVES   64
#define N_INTERNAL 63

#define CHILD_EPS  2.2204460492503131e-16
#define BYPASS_TH  0.9999999999999998   /* 1 - DBL_EPSILON */
#define CLAMP_V    1e300
#define PI_F       3.14159265358979f
#define LN2_F      0.69314718056f

// Folded parameters (built by prep kernel).
static __device__ double g_g  [N_INTERNAL * 8];  // folded gates (double, for fold step)
static __device__ float4 g_gf4[126];             // per side: (p0,p1,p2,p3) as float
static __device__ float4 g_r0f[N_LEAVES];        // round-0 folded coeffs per leaf

// 2/pi fraction bits (fdlibm two_over_pi), prepended zero word.
static __device__ const unsigned long long PH_TAB[21] = {
    0x0000000000000000ULL,
    0xA2F9836E4E441529ULL, 0xFC2757D1F534DDC0ULL, 0xDB6295993C439041ULL,
    0xFE5163ABDEBBC561ULL, 0xB7246E3A424DD2E0ULL, 0x06492EEA09D1921CULL,
    0xFE1DEB1CB129A73EULL, 0xE88235F52EBB4484ULL, 0xE99C7026B45F7E41ULL,
    0x3991D639835339F4ULL, 0x9C845F8BBDF9283BULL, 0x1FF897FFDE05980FULL,
    0xEF2F118B5A0A6D1FULL, 0x6D367ECF27CB09B7ULL, 0x4F463F669E5FEA2DULL,
    0x7527BAC7EBE5F17BULL, 0x3D0739F78A5292EAULL, 0x6BFB5FB11F8D5D08ULL,
    0x56033046FC7B6BABULL, 0xF0CFBC209AF4361DULL
};

// NaN unreachable post-round-0 -> pure min/max clamp matches nan_to_num+clip.
__device__ __forceinline__ double clampd(double v) {
    return fmin(fmax(v, -CLAMP_V), CLAMP_V);
}

// 2^k as double via high-word construct (single 32-bit shift).
__device__ __forceinline__ double pow2k(int kbiased) {
    return __hiloint2double(kbiased << 20, 0);
}

// Branchless fp32 atan2: swap-trick + deg-11 odd minimax poly (~1e-7 rad).
// Quadrant fixups via selects; copysignf preserves +-0 imag conventions.
__device__ __forceinline__ float fast_atan2f(float y, float x) {
    float ax = fabsf(x), ay = fabsf(y);
    float mx = fmaxf(ax, ay), mn = fminf(ax, ay);
    float t  = __fdividef(mn, fmaxf(mx, 1e-38f));
    float s  = t * t;
    float p  = fmaf(s, -0.01172120f, 0.05265332f);
    p = fmaf(s, p, -0.11643287f);
    p = fmaf(s, p,  0.19354346f);
    p = fmaf(s, p, -0.33262347f);
    p = fmaf(s, p,  0.99997726f);
    float r = t * p;
    r = (ay > ax)   ? (1.57079632679f - r) : r;
    r = (x < 0.0f)  ? (3.14159265359f - r) : r;
    return copysignf(r, y);
}

// Branchy sincos (float outputs): Cody-Waite (<1e6, single-DFMA) or 128-bit PH.
__device__ __forceinline__ void fast_sincos(const unsigned long long* __restrict__ ph,
                                            double a, float& sf, float& cf) {
    double aa = fabs(a);
    if (aa < 1.0e6) {
        double kd = rint(a * 0.15915494309189535);
        double r  = fma(-kd, 6.283185307179586, a);
        __sincosf((float)r, &sf, &cf);
    } else {
        int hi = __double2hiint(aa);
        int E  = hi >> 20;                                  // biased exp (aa>0)
        unsigned long long ix = (__double_as_longlong(aa) & 0xFFFFFFFFFFFFFULL) | (1ULL << 52);
        int q = E - 1013;
        int i = q >> 6, sh = q & 63;
        unsigned long long p0 = ph[i], p1 = ph[i+1], p2 = ph[i+2];
        unsigned long long w0 = (p0 << sh) | ((p1 >> 1) >> (63 - sh));
        unsigned long long w1 = (p1 << sh) | ((p2 >> 1) >> (63 - sh));
        unsigned long long fhi = ix * w0 + __umul64hi(ix, w1);
        double fr  = (double)(long long)fhi * 5.421010862427522e-20;   // [-0.5,0.5)
        double ang = fr * 6.283185307179586;
        __sincosf((float)ang, &sf, &cf);
        sf = (a < 0.0) ? -sf : sf;
    }
}

// ---------------------------------------------------------------------------
// Prep: dtype detect, softmaxes, bypass-fold gates, fold leaves into round-0.
// ---------------------------------------------------------------------------
__global__ void prep_kernel(const void* __restrict__ leafv,
                            const void* __restrict__ gatev,
                            float* __restrict__ out,
                            int tail_mode, long long tail_off) {
    __shared__ int    s_is_f32;
    __shared__ double s_w[N_LEAVES * 3];
    int t = threadIdx.x;

    if (t == 0) {
        const float* lf = (const float*)leafv;
        int cnt = 0;
        for (int i = 0; i < 64; ++i) {
            float v = fabsf(lf[i]);
            if (isfinite(v) && v > 1e-4f && v < 100.0f) ++cnt;
        }
        s_is_f32 = (cnt >= 52) ? 1 : 0;
    }
    __syncthreads();
    const int f32w = s_is_f32;
    const float*  lf = (const float*) leafv;
    const double* ld = (const double*)leafv;
    const float*  gf = (const float*) gatev;
    const double* gd = (const double*)gatev;

    if (t < N_LEAVES) {
        double a = f32w ? (double)lf[3*t]   : ld[3*t];
        double b = f32w ? (double)lf[3*t+1] : ld[3*t+1];
        double c = f32w ? (double)lf[3*t+2] : ld[3*t+2];
        double m = fmax(a, fmax(b, c));
        double ea = exp(a - m), eb = exp(b - m), ec = exp(c - m);
        double inv = 1.0 / (ea + eb + ec);
        double w[3] = {ea*inv, eb*inv, ec*inv};
        for (int j = 0; j < 3; ++j) {
            s_w[3*t+j] = w[j];
            if (tail_mode == 1) out[tail_off + 3*t + j] = (float)w[j];
        }
    } else if (t < N_LEAVES + 2*N_INTERNAL) {
        int g = t - N_LEAVES;                      // 0..125
        double v0 = f32w ? (double)gf[4*g]   : gd[4*g];
        double v1 = f32w ? (double)gf[4*g+1] : gd[4*g+1];
        double v2 = f32w ? (double)gf[4*g+2] : gd[4*g+2];
        double v3 = f32w ? (double)gf[4*g+3] : gd[4*g+3];
        double m = fmax(fmax(v0, v1), fmax(v2, v3));
        double e0 = exp(v0-m), e1 = exp(v1-m), e2 = exp(v2-m), e3 = exp(v3-m);
        double inv = 1.0 / (e0 + e1 + e2 + e3);
        double p0 = e0*inv, p1 = e1*inv, p2 = e2*inv, p3 = e3*inv;
        if (tail_mode == 1) {
            out[tail_off + 3*N_LEAVES + 4*g]   = (float)p0;
            out[tail_off + 3*N_LEAVES + 4*g+1] = (float)p1;
            out[tail_off + 3*N_LEAVES + 4*g+2] = (float)p2;
            out[tail_off + 3*N_LEAVES + 4*g+3] = (float)p3;
        }
        if (p0 > BYPASS_TH) { p0 = 1.0; p1 = 0.0; p2 = 0.0; p3 = 0.0; }
        if (p1 > BYPASS_TH) { p0 = 0.0; p1 = 1.0; p2 = 0.0; p3 = 0.0; }
        if (p2 > BYPASS_TH) { p0 = 0.0; p1 = 0.0; p2 = 1.0; p3 = 0.0; }
        if (!(p3 > CHILD_EPS)) p3 = 0.0;
        g_g[4*g]   = p0; g_g[4*g+1] = p1; g_g[4*g+2] = p2; g_g[4*g+3] = p3;
        g_gf4[g]   = make_float4((float)p0, (float)p1, (float)p2, (float)p3);
    }
    __syncthreads();

    if (t < N_LEAVES) {
        const double* gp = &g_g[(t >> 1) * 8 + (t & 1) * 4];
        double c0 = gp[0] + gp[3] * s_w[3*t];
        double c1 = gp[1] + gp[3] * s_w[3*t+1];
        double c2 = gp[2] + gp[3] * s_w[3*t+2];
        g_r0f[t] = make_float4((float)c0, (float)c1, (float)c2, 0.0f);
    }
}

// ---------------------------------------------------------------------------
// Round-1 node: children fp32 (|re| <= ~2e11, im in {0,-pi}).
// ---------------------------------------------------------------------------
__device__ __forceinline__ void eval_node_r1(const float4* __restrict__ sf4,
                                             int node,
                                             float clrf, float clif,
                                             float crrf, float crif,
                                             float x0f, float x1f,
                                             double& olr, double& oli) {
    float4 L = sf4[2*node], R = sf4[2*node+1];
    float basel = fmaf(L.y, x0f, fmaf(L.z, x1f, L.x));
    float baser = fmaf(R.y, x0f, fmaf(R.z, x1f, R.x));
    float alr = fmaf(L.w, clrf, basel);
    float ali = L.w * clif;                         // |ali| <= pi
    float brr = fmaf(R.w, crrf, baser);
    float bri = R.w * crif;
    float ac  = fminf(fmaxf(alr, -708.0f), 709.7f);
    float kdf = rintf(ac * 1.44269504f);
    float rf  = fmaf(-kdf, 0.693115234375f, ac);
    rf        = fmaf(-kdf, 3.1946183e-5f, rf);
    float ef2 = exp2f(fmaf(rf, 1.44269504f, 1.0f));   // 2*e^rf
    double sden = pow2k((int)kdf + 1022);
    float sf, cf;
    __sincosf(ali, &sf, &cf);
    float m2  = fmaxf(fmaf(brr, brr, bri * bri), 1.2e-38f);
    float grf = 0.5f * __log2f(m2) * LN2_F;
    float gif = fast_atan2f(bri, brr);
    olr = clampd(fma((double)(ef2 * cf), sden, -(double)grf));
    oli = clampd(fma((double)(ef2 * sf), sden, -(double)gif));
}

// ---------------------------------------------------------------------------
// Full-range node (rounds 2-5): fp32-steered exp reduction, fp32 clog epilogue.
// ---------------------------------------------------------------------------
__device__ __forceinline__ void eval_node_full(const float4* __restrict__ sf4,
                                               int node,
                                               const unsigned long long* __restrict__ ph,
                                               double clr, double cli,
                                               double crr, double cri,
                                               float x0f, float x1f,
                                               double& olr, double& oli) {
    float4 L = sf4[2*node], R = sf4[2*node+1];
    double p3l = (double)L.w, p3r = (double)R.w;
    float basel = fmaf(L.y, x0f, fmaf(L.z, x1f, L.x));
    float baser = fmaf(R.y, x0f, fmaf(R.z, x1f, R.x));
    double alr = fma(p3l, clr, (double)basel);
    double ali = p3l * cli;
    double brr = fma(p3r, crr, (double)baser);
    double bri = p3r * cri;
    // exp(alr): kd from fp32 image; r from DOUBLE alr (single DFMA); fp32 clamp.
    float acf = fminf(fmaxf((float)alr, -708.0f), 709.7f);
    float kdf = rintf(acf * 1.44269504f);
    double r  = fma(-(double)kdf, 0.6931471805599453, alr);
    float rfc = fminf(fmaxf((float)r, -90.0f), 90.0f);   // bound saturated args
    float ef2 = exp2f(fmaf(rfc, 1.44269504f, 1.0f));     // 2*e^r
    double sden = pow2k((int)kdf + 1022);
    float sf, cf;
    fast_sincos(ph, ali, sf, cf);
    // clog with 2^k scaling; exponents via high words only.
    int ex = (__double2hiint(brr) >> 20) & 0x7ff;
    int ey = (__double2hiint(bri) >> 20) & 0x7ff;
    int em = ex > ey ? ex : ey;
    double sc = pow2k(2045 - em);                           // 2^(1022-em)
    float xsf = (float)(brr * sc), ysf = (float)(bri * sc);
    float m2  = fmaxf(fmaf(xsf, xsf, ysf * ysf), 1.2e-38f);
    float grf = fmaf(0.5f, __log2f(m2), (float)(em - 1022)) * LN2_F;
    float gif = fast_atan2f(ysf, xsf);
    olr = clampd(fma((double)(ef2 * cf), sden, -(double)grf));
    oli = clampd(fma((double)(ef2 * sf), sden, -(double)gif));
}

// ---------------------------------------------------------------------------
// Main kernel: 2 lanes per element; lane-local through round 4, one shfl.
// ---------------------------------------------------------------------------
__global__ __launch_bounds__(128)
void tree_kernel(const float* __restrict__ x, float* __restrict__ out,
                 int interleaved) {
    __shared__ float4 sr0[N_LEAVES];
    __shared__ float4 sf4[126];
    __shared__ unsigned long long sph[21];
    int tid = threadIdx.x;
    for (int i = tid; i < N_LEAVES; i += 128) sr0[i] = g_r0f[i];
    for (int i = tid; i < 126; i += 128)      sf4[i] = g_gf4[i];
    if (tid < 21) sph[tid] = PH_TAB[tid];
    __syncthreads();

    int g    = blockIdx.x * 128 + tid;
    int e    = g >> 1;
    int lane = g & 1;

    float x0f = x[2*e];
    float x1f = x[2*e+1];

    // Round 0: 16 real pairs for this lane, fully fp32.
    float lrf[16], lif[16];
#pragma unroll
    for (int k = 0; k < 16; ++k) {
        int gk = 16*lane + k;
        float4 L = sr0[2*gk], R = sr0[2*gk+1];
        float bl = fmaf(L.y, x0f, fmaf(L.z, x1f, L.x));
        float br = fmaf(R.y, x0f, fmaf(R.z, x1f, R.x));
        float er = __expf(bl);
        float gr = __log2f(fmaxf(fabsf(br), 1e-30f)) * LN2_F;
        lrf[k] = er - gr;
        lif[k] = signbit(br) ? -PI_F : 0.0f;
    }

    // Round 1: 8 fp32 front-end nodes; outputs become double.
    double lr[8], li[8];
#pragma unroll
    for (int j = 0; j < 8; ++j)
        eval_node_r1(sf4, 32 + 8*lane + j,
                     lrf[2*j], lif[2*j], lrf[2*j+1], lif[2*j+1],
                     x0f, x1f, lr[j], li[j]);

    // Round 2: 4 nodes.
#pragma unroll
    for (int j = 0; j < 4; ++j)
        eval_node_full(sf4, 48 + 4*lane + j, sph,
                       lr[2*j], li[2*j], lr[2*j+1], li[2*j+1],
                       x0f, x1f, lr[j], li[j]);

    // Round 3: 2 nodes.
#pragma unroll
    for (int j = 0; j < 2; ++j)
        eval_node_full(sf4, 56 + 2*lane + j, sph,
                       lr[2*j], li[2*j], lr[2*j+1], li[2*j+1],
                       x0f, x1f, lr[j], li[j]);

    // Round 4: 1 node, still lane-local.
    eval_node_full(sf4, 60 + lane, sph,
                   lr[0], li[0], lr[1], li[1], x0f, x1f, lr[0], li[0]);

    // Round 5: node 62; right child comes from lane 1 via shfl.
    {
        double pr = __shfl_xor_sync(0xffffffffu, lr[0], 1);
        double pi = __shfl_xor_sync(0xffffffffu, li[0], 1);
        eval_node_full(sf4, 62, sph,
                       lr[0], li[0], pr, pi, x0f, x1f, lr[0], li[0]);
    }

    if (lane == 0) {
        if (interleaved) {
            out[2*e]   = (float)lr[0];
            out[2*e+1] = (float)li[0];
        } else {
            out[e] = (float)lr[0];
        }
    }
}

// ---------------------------------------------------------------------------
extern "C" void kernel_launch(void* const* d_in, const int* in_sizes, int n_in,
                              void* d_out, int out_size) {
    const float* x    = nullptr;
    const void*  leaf = nullptr;
    const void*  gate = nullptr;
    for (int i = 0; i < n_in; ++i) {
        if      (in_sizes[i] == 2 * BATCH)      x    = (const float*)d_in[i];
        else if (in_sizes[i] == 3 * N_LEAVES)   leaf = d_in[i];
        else if (in_sizes[i] == 8 * N_INTERNAL) gate = d_in[i];
    }
    if (!x || !leaf || !gate) return;

    float* out = (float*)d_out;

    const int NPROB = 3*N_LEAVES + 8*N_INTERNAL;  // 696
    int interleaved, tail_mode = 0;
    long long tail_off = 0;

    if (out_size >= 2*BATCH + NPROB) {
        interleaved = 1; tail_mode = 1; tail_off = 2*BATCH;
    } else if (out_size >= 2*BATCH) {
        interleaved = 1;
    } else if (out_size >= BATCH + NPROB) {
        interleaved = 0; tail_mode = 1; tail_off = BATCH;
    } else {
        interleaved = 0;
    }

    prep_kernel<<<1, 192>>>(leaf, gate, out, tail_mode, tail_off);
    tree_kernel<<<(BATCH*2)/128, 128>>>(x, out, interleaved);
}